// round 14
// baseline (speedup 1.0000x reference)
#include <cuda_runtime.h>
#include <cuda_bf16.h>
#include <cuda_fp16.h>
#include <cstdint>

#define T_SEQ 2048
#define EMB   2048
#define NH    16
#define HD    128
#define LAT   64

// ---------------- scratch (static device globals; no allocation) ----------------
__device__ float g_q2lT[NH * LAT * HD];
__device__ float g_lpart[8 * T_SEQ * 2 * LAT];
__device__ float g_qsum[T_SEQ * NH];
__device__ float g_ksum[T_SEQ];
// fold inputs: bf16 [hi|lo] (kept high-precision; tiny)
__device__ __align__(16) __nv_bfloat16 g_WqT2 [EMB * NH * 2 * HD];
__device__ __align__(16) __nv_bfloat16 g_Wo2  [EMB * NH * 2 * HD];
__device__ __align__(16) __nv_bfloat16 g_q2l2p[NH * HD * 2 * HD];
__device__ __align__(16) __nv_bfloat16 g_vup2p[NH * HD * 2 * HD];
// fp16 single-precision activation path
__device__ __align__(16) __half g_hidh [T_SEQ * EMB];        // 8 MB
__device__ __align__(16) __half g_Wkvh [2 * LAT * EMB];      // 0.5 MB
__device__ __align__(16) __half g_Wf1h [NH * LAT * EMB];     // 4 MB
__device__ __align__(16) __half g_Wf2h [EMB * NH * LAT];     // 4 MB
__device__ __align__(16) __half g_qlath[T_SEQ * NH * 2 * LAT]; // 8 MB: [t][h][ hi(64) | lo(64) ]
__device__ __align__(16) __half g_lkh  [T_SEQ * LAT];        // 0.25 MB
__device__ __align__(16) __half g_lvTh [LAT * T_SEQ];        // V^T
__device__ __align__(16) __half g_lctxh[T_SEQ * NH * LAT];   // 4 MB

// ================= PTX helpers =================
__device__ __forceinline__ uint32_t smem_u32(const void* p) {
    uint32_t a;
    asm("{ .reg .u64 t; cvta.to.shared.u64 t, %1; cvt.u32.u64 %0, t; }" : "=r"(a) : "l"(p));
    return a;
}
#define CP_ASYNC16(dst, src) \
    asm volatile("cp.async.cg.shared.global [%0], [%1], 16;" :: "r"(dst), "l"(src))
#define CP_COMMIT() asm volatile("cp.async.commit_group;")
#define CP_WAIT1()  asm volatile("cp.async.wait_group 1;")
#define CP_WAIT0()  asm volatile("cp.async.wait_group 0;")

__device__ __forceinline__ void ldmx4(uint32_t& r0, uint32_t& r1, uint32_t& r2, uint32_t& r3,
                                      uint32_t addr) {
    asm volatile("ldmatrix.sync.aligned.m8n8.x4.shared.b16 {%0,%1,%2,%3}, [%4];"
                 : "=r"(r0), "=r"(r1), "=r"(r2), "=r"(r3) : "r"(addr));
}
__device__ __forceinline__ void mma16816(float* d, const uint32_t* a, const uint32_t* b) {
    asm volatile("mma.sync.aligned.m16n8k16.row.col.f32.bf16.bf16.f32 "
                 "{%0,%1,%2,%3}, {%4,%5,%6,%7}, {%8,%9}, {%0,%1,%2,%3};"
                 : "+f"(d[0]), "+f"(d[1]), "+f"(d[2]), "+f"(d[3])
                 : "r"(a[0]), "r"(a[1]), "r"(a[2]), "r"(a[3]), "r"(b[0]), "r"(b[1]));
}
__device__ __forceinline__ void mma16816h(float* d, const uint32_t* a, const uint32_t* b) {
    asm volatile("mma.sync.aligned.m16n8k16.row.col.f32.f16.f16.f32 "
                 "{%0,%1,%2,%3}, {%4,%5,%6,%7}, {%8,%9}, {%0,%1,%2,%3};"
                 : "+f"(d[0]), "+f"(d[1]), "+f"(d[2]), "+f"(d[3])
                 : "r"(a[0]), "r"(a[1]), "r"(a[2]), "r"(a[3]), "r"(b[0]), "r"(b[1]));
}

// ---------------- fp32 -> fp16 convert ----------------
__global__ void cvt_f16(const float* __restrict__ x, __half* __restrict__ out, int n)
{
    int i = (blockIdx.x * blockDim.x + threadIdx.x) * 4;
    if (i >= n) return;
    float4 v = *(const float4*)(x + i);
    __half2 a = __floats2half2_rn(v.x, v.y);
    __half2 b = __floats2half2_rn(v.z, v.w);
    uint2 pk;
    pk.x = *(uint32_t*)&a; pk.y = *(uint32_t*)&b;
    *(uint2*)(out + i) = pk;
}

// ---------------- fp32 -> [hi|lo] bf16 split (fold inputs) ----------------
__global__ void cvt_split2(const float* __restrict__ x, __nv_bfloat16* __restrict__ out,
                           int total, int K, int offL)
{
    int i = (blockIdx.x * blockDim.x + threadIdx.x) * 4;
    if (i >= total) return;
    float4 v = *(const float4*)(x + i);
    float vv[4] = {v.x, v.y, v.z, v.w};
    __nv_bfloat16 hb[4], lb[4];
#pragma unroll
    for (int k = 0; k < 4; k++) {
        hb[k] = __float2bfloat16(vv[k]);
        lb[k] = __float2bfloat16(vv[k] - __bfloat162float(hb[k]));
    }
    int r = i / K, c = i - r * K;
    size_t base = (size_t)r * 2 * K + c;
    *(uint2*)(out + base)        = *(uint2*)hb;
    *(uint2*)(out + base + offL) = *(uint2*)lb;
}

__global__ void cvt_split2_pad(const float* __restrict__ x, __nv_bfloat16* __restrict__ out,
                               int nb, int rows, int K, int padRows, int offL)
{
    int i = (blockIdx.x * blockDim.x + threadIdx.x) * 4;
    int total = nb * padRows * K;
    if (i >= total) return;
    int b = i / (padRows * K);
    int rem = i - b * (padRows * K);
    int r = rem / K, c = rem - r * K;
    float vv[4] = {0.f, 0.f, 0.f, 0.f};
    if (r < rows) {
        float4 v = *(const float4*)(x + (size_t)b * rows * K + (size_t)r * K + c);
        vv[0] = v.x; vv[1] = v.y; vv[2] = v.z; vv[3] = v.w;
    }
    __nv_bfloat16 hb[4], lb[4];
#pragma unroll
    for (int k = 0; k < 4; k++) {
        hb[k] = __float2bfloat16(vv[k]);
        lb[k] = __float2bfloat16(vv[k] - __bfloat162float(hb[k]));
    }
    size_t base = (size_t)b * padRows * 2 * K + (size_t)r * 2 * K + c;
    *(uint2*)(out + base)        = *(uint2*)hb;
    *(uint2*)(out + base + offL) = *(uint2*)lb;
}

// ---- fused transpose + split: Wq [hd][e] -> WqT2 [e][h][256] ([hi|lo]) ----
__global__ void transpose_split2(const float* __restrict__ in, __nv_bfloat16* __restrict__ out)
{
    __shared__ float t[32][33];
    int x = blockIdx.x * 32 + threadIdx.x;
    for (int i = threadIdx.y; i < 32; i += 8) {
        int y = blockIdx.y * 32 + i;
        t[i][threadIdx.x] = in[(size_t)y * EMB + x];
    }
    __syncthreads();
    for (int i = threadIdx.y; i < 32; i += 8) {
        int eo = blockIdx.x * 32 + i;
        int hd = blockIdx.y * 32 + threadIdx.x;
        float v = t[threadIdx.x][i];
        __nv_bfloat16 h = __float2bfloat16(v);
        __nv_bfloat16 l = __float2bfloat16(v - __bfloat162float(h));
        int hh = hd >> 7, d = hd & 127;
        size_t base = (size_t)eo * (NH * 2 * HD) + hh * 256 + d;
        out[base]       = h;
        out[base + 128] = l;
    }
}

// ---------------- batched tiled transpose (fp32) ----------------
__global__ void transpose_k(const float* __restrict__ in, float* __restrict__ out,
                            int R, int C, long bIn, long bOut)
{
    __shared__ float t[32][33];
    in  += (long)blockIdx.z * bIn;
    out += (long)blockIdx.z * bOut;
    int x = blockIdx.x * 32 + threadIdx.x;
    for (int i = threadIdx.y; i < 32; i += 8) {
        int y = blockIdx.y * 32 + i;
        if (y < R && x < C) t[i][threadIdx.x] = in[(size_t)y * C + x];
    }
    __syncthreads();
    for (int i = threadIdx.y; i < 32; i += 8) {
        int y2 = blockIdx.x * 32 + i;
        int x2 = blockIdx.y * 32 + threadIdx.x;
        if (y2 < C && x2 < R) out[(size_t)y2 * R + x2] = t[threadIdx.x][i];
    }
}

#define GS 72
#define STAGE_ELTS (128 * GS)
#define HMMA_SMEM (3 * 2 * STAGE_ELTS * 2)

// ==== HMMA fold GEMM (bf16x3 phase-mapped) -> single fp16 output ====
__global__ __launch_bounds__(256) void hmma_fold(
    const __nv_bfloat16* __restrict__ A, const __nv_bfloat16* __restrict__ B,
    __half* __restrict__ Ch, int Ka, int lda, int ldb,
    long batchA, long batchB, long batchC,
    int ldc, int validM, int validN)
{
    extern __shared__ __align__(16) __nv_bfloat16 sm[];
    const int tid = threadIdx.x;
    const int wid = tid >> 5;
    const int lane = tid & 31;
    const int warp_m = wid >> 2;
    const int warp_n = wid & 3;
    const int bm = blockIdx.y * 128;
    const int bn = blockIdx.x * 128;
    const uint32_t sbase = smem_u32(sm);

    A  += (size_t)blockIdx.z * batchA;
    B  += (size_t)blockIdx.z * batchB;
    Ch += (size_t)blockIdx.z * batchC;
    const int nk = (3 * Ka) >> 6;

    auto load_stage = [&](int stage, int k0) {
        __nv_bfloat16* As = sm + stage * 2 * STAGE_ELTS;
        __nv_bfloat16* Bs = As + STAGE_ELTS;
        int p = (k0 >= 2 * Ka) ? 2 : (k0 >= Ka ? 1 : 0);
        int kloc = k0 - p * Ka;
        const __nv_bfloat16* Ap = A + ((p == 1) ? Ka : 0) + kloc;
        const __nv_bfloat16* Bp = B + ((p == 2) ? Ka : 0) + kloc;
#pragma unroll
        for (int i = 0; i < 4; i++) {
            int c = tid + i * 256;
            int row = c >> 3;
            int col8 = (c & 7) * 8;
            CP_ASYNC16(smem_u32(As + row * GS + col8), Ap + (size_t)(bm + row) * lda + col8);
            CP_ASYNC16(smem_u32(Bs + row * GS + col8), Bp + (size_t)(bn + row) * ldb + col8);
        }
    };

    float acc[4][4][4];
#pragma unroll
    for (int mi = 0; mi < 4; mi++)
#pragma unroll
        for (int ni = 0; ni < 4; ni++)
#pragma unroll
            for (int r = 0; r < 4; r++) acc[mi][ni][r] = 0.f;

    load_stage(0, 0); CP_COMMIT();
    if (nk > 1) { load_stage(1, 64); CP_COMMIT(); }

    const int a_row = (lane & 15);
    const int a_koff = (lane >> 4) * 8;
    const int b_row = (lane & 7) + ((lane >> 4) & 1) * 8;
    const int b_koff = ((lane >> 3) & 1) * 8;

    for (int it = 0; it < nk; it++) {
        CP_WAIT1();
        __syncthreads();
        if (it + 2 < nk) { load_stage((it + 2) % 3, (it + 2) * 64); CP_COMMIT(); }

        const int stage = it % 3;
        const uint32_t sA = sbase + (uint32_t)(stage * 2 * STAGE_ELTS) * 2;
        const uint32_t sB = sA + STAGE_ELTS * 2;

#pragma unroll
        for (int kk = 0; kk < 64; kk += 16) {
            uint32_t af[4][4];
#pragma unroll
            for (int mi = 0; mi < 4; mi++) {
                uint32_t addr = sA + ((warp_m * 64 + mi * 16 + a_row) * GS + kk + a_koff) * 2;
                ldmx4(af[mi][0], af[mi][1], af[mi][2], af[mi][3], addr);
            }
            uint32_t bf[4][2];
#pragma unroll
            for (int ni2 = 0; ni2 < 2; ni2++) {
                uint32_t addr = sB + ((warp_n * 32 + ni2 * 16 + b_row) * GS + kk + b_koff) * 2;
                uint32_t r0, r1, r2, r3;
                ldmx4(r0, r1, r2, r3, addr);
                bf[ni2 * 2 + 0][0] = r0; bf[ni2 * 2 + 0][1] = r1;
                bf[ni2 * 2 + 1][0] = r2; bf[ni2 * 2 + 1][1] = r3;
            }
#pragma unroll
            for (int mi = 0; mi < 4; mi++)
#pragma unroll
                for (int ni = 0; ni < 4; ni++)
                    mma16816(acc[mi][ni], af[mi], bf[ni]);
        }
        __syncthreads();
    }

    const int er = lane >> 2;
    const int ec = (lane & 3) * 2;
#pragma unroll
    for (int mi = 0; mi < 4; mi++) {
#pragma unroll
        for (int ni = 0; ni < 4; ni++) {
            int n0 = bn + warp_n * 32 + ni * 8 + ec;
            if (n0 >= validN) continue;
#pragma unroll
            for (int rr = 0; rr < 2; rr++) {
                int m0 = bm + warp_m * 64 + mi * 16 + er + rr * 8;
                if (m0 >= validM) continue;
                __half2 hp = __floats2half2_rn(acc[mi][ni][rr * 2 + 0],
                                               acc[mi][ni][rr * 2 + 1]);
                *(__half2*)(Ch + (size_t)m0 * ldc + n0) = hp;
            }
        }
    }
}

// ============== plain fp16 HMMA GEMM (+split-K): C fp32 = A @ B^T ==============
__global__ __launch_bounds__(256) void hmma_gemm_f16(
    const __half* __restrict__ A, const __half* __restrict__ B,
    float* __restrict__ C, int M, int N, int K, int nsplit)
{
    extern __shared__ __align__(16) __half smh[];
    const int tid = threadIdx.x;
    const int wid = tid >> 5;
    const int lane = tid & 31;
    const int warp_m = wid >> 2;
    const int warp_n = wid & 3;
    const int bm = blockIdx.y * 128;
    const int bn = blockIdx.x * 128;
    const uint32_t sbase = smem_u32(smh);

    const int Kc = K / nsplit;
    const int kbeg = blockIdx.z * Kc;
    C += (size_t)blockIdx.z * M * N;
    const int nk = Kc >> 6;

    auto load_stage = [&](int stage, int k0) {
        __half* As = smh + stage * 2 * STAGE_ELTS;
        __half* Bs = As + STAGE_ELTS;
#pragma unroll
        for (int i = 0; i < 4; i++) {
            int c = tid + i * 256;
            int row = c >> 3;
            int col8 = (c & 7) * 8;
            CP_ASYNC16(smem_u32(As + row * GS + col8),
                       A + (size_t)(bm + row) * K + kbeg + k0 + col8);
            CP_ASYNC16(smem_u32(Bs + row * GS + col8),
                       B + (size_t)(bn + row) * K + kbeg + k0 + col8);
        }
    };

    float acc[4][4][4];
#pragma unroll
    for (int mi = 0; mi < 4; mi++)
#pragma unroll
        for (int ni = 0; ni < 4; ni++)
#pragma unroll
            for (int r = 0; r < 4; r++) acc[mi][ni][r] = 0.f;

    load_stage(0, 0); CP_COMMIT();
    if (nk > 1) { load_stage(1, 64); CP_COMMIT(); }

    const int a_row = (lane & 15);
    const int a_koff = (lane >> 4) * 8;
    const int b_row = (lane & 7) + ((lane >> 4) & 1) * 8;
    const int b_koff = ((lane >> 3) & 1) * 8;

    for (int it = 0; it < nk; it++) {
        CP_WAIT1();
        __syncthreads();
        if (it + 2 < nk) { load_stage((it + 2) % 3, (it + 2) * 64); CP_COMMIT(); }

        const int stage = it % 3;
        const uint32_t sA = sbase + (uint32_t)(stage * 2 * STAGE_ELTS) * 2;
        const uint32_t sB = sA + STAGE_ELTS * 2;

#pragma unroll
        for (int kk = 0; kk < 64; kk += 16) {
            uint32_t af[4][4];
#pragma unroll
            for (int mi = 0; mi < 4; mi++) {
                uint32_t addr = sA + ((warp_m * 64 + mi * 16 + a_row) * GS + kk + a_koff) * 2;
                ldmx4(af[mi][0], af[mi][1], af[mi][2], af[mi][3], addr);
            }
            uint32_t bf[4][2];
#pragma unroll
            for (int ni2 = 0; ni2 < 2; ni2++) {
                uint32_t addr = sB + ((warp_n * 32 + ni2 * 16 + b_row) * GS + kk + b_koff) * 2;
                uint32_t r0, r1, r2, r3;
                ldmx4(r0, r1, r2, r3, addr);
                bf[ni2 * 2 + 0][0] = r0; bf[ni2 * 2 + 0][1] = r1;
                bf[ni2 * 2 + 1][0] = r2; bf[ni2 * 2 + 1][1] = r3;
            }
#pragma unroll
            for (int mi = 0; mi < 4; mi++)
#pragma unroll
                for (int ni = 0; ni < 4; ni++)
                    mma16816h(acc[mi][ni], af[mi], bf[ni]);
        }
        __syncthreads();
    }

    const int er = lane >> 2;
    const int ec = (lane & 3) * 2;
#pragma unroll
    for (int mi = 0; mi < 4; mi++) {
#pragma unroll
        for (int ni = 0; ni < 4; ni++) {
            int m0 = bm + warp_m * 64 + mi * 16 + er;
            int n0 = bn + warp_n * 32 + ni * 8 + ec;
            *(float2*)(C + (size_t)m0 * N + n0) = make_float2(acc[mi][ni][0], acc[mi][ni][1]);
            *(float2*)(C + (size_t)(m0 + 8) * N + n0) = make_float2(acc[mi][ni][2], acc[mi][ni][3]);
        }
    }
}

// ==== hmma_qlat_f16: qlat GEMM writing fp16 [hi|lo] pairs: [t][h][ hi(64) | lo(64) ] ====
__global__ __launch_bounds__(256) void hmma_qlat_f16(
    const __half* __restrict__ A, const __half* __restrict__ B,
    __half* __restrict__ Qh, int K)
{
    extern __shared__ __align__(16) __half smh[];
    const int tid = threadIdx.x;
    const int wid = tid >> 5;
    const int lane = tid & 31;
    const int warp_m = wid >> 2;
    const int warp_n = wid & 3;
    const int bm = blockIdx.y * 128;
    const int bn = blockIdx.x * 128;
    const uint32_t sbase = smem_u32(smh);
    const int nk = K >> 6;

    auto load_stage = [&](int stage, int k0) {
        __half* As = smh + stage * 2 * STAGE_ELTS;
        __half* Bs = As + STAGE_ELTS;
#pragma unroll
        for (int i = 0; i < 4; i++) {
            int c = tid + i * 256;
            int row = c >> 3;
            int col8 = (c & 7) * 8;
            CP_ASYNC16(smem_u32(As + row * GS + col8),
                       A + (size_t)(bm + row) * K + k0 + col8);
            CP_ASYNC16(smem_u32(Bs + row * GS + col8),
                       B + (size_t)(bn + row) * K + k0 + col8);
        }
    };

    float acc[4][4][4];
#pragma unroll
    for (int mi = 0; mi < 4; mi++)
#pragma unroll
        for (int ni = 0; ni < 4; ni++)
#pragma unroll
            for (int r = 0; r < 4; r++) acc[mi][ni][r] = 0.f;

    load_stage(0, 0); CP_COMMIT();
    if (nk > 1) { load_stage(1, 64); CP_COMMIT(); }

    const int a_row = (lane & 15);
    const int a_koff = (lane >> 4) * 8;
    const int b_row = (lane & 7) + ((lane >> 4) & 1) * 8;
    const int b_koff = ((lane >> 3) & 1) * 8;

    for (int it = 0; it < nk; it++) {
        CP_WAIT1();
        __syncthreads();
        if (it + 2 < nk) { load_stage((it + 2) % 3, (it + 2) * 64); CP_COMMIT(); }

        const int stage = it % 3;
        const uint32_t sA = sbase + (uint32_t)(stage * 2 * STAGE_ELTS) * 2;
        const uint32_t sB = sA + STAGE_ELTS * 2;

#pragma unroll
        for (int kk = 0; kk < 64; kk += 16) {
            uint32_t af[4][4];
#pragma unroll
            for (int mi = 0; mi < 4; mi++) {
                uint32_t addr = sA + ((warp_m * 64 + mi * 16 + a_row) * GS + kk + a_koff) * 2;
                ldmx4(af[mi][0], af[mi][1], af[mi][2], af[mi][3], addr);
            }
            uint32_t bf[4][2];
#pragma unroll
            for (int ni2 = 0; ni2 < 2; ni2++) {
                uint32_t addr = sB + ((warp_n * 32 + ni2 * 16 + b_row) * GS + kk + b_koff) * 2;
                uint32_t r0, r1, r2, r3;
                ldmx4(r0, r1, r2, r3, addr);
                bf[ni2 * 2 + 0][0] = r0; bf[ni2 * 2 + 0][1] = r1;
                bf[ni2 * 2 + 1][0] = r2; bf[ni2 * 2 + 1][1] = r3;
            }
#pragma unroll
            for (int mi = 0; mi < 4; mi++)
#pragma unroll
                for (int ni = 0; ni < 4; ni++)
                    mma16816h(acc[mi][ni], af[mi], bf[ni]);
        }
        __syncthreads();
    }

    const int er = lane >> 2;
    const int ec = (lane & 3) * 2;
#pragma unroll
    for (int mi = 0; mi < 4; mi++) {
#pragma unroll
        for (int ni = 0; ni < 4; ni++) {
            int n0 = bn + warp_n * 32 + ni * 8 + ec;
            int h = n0 >> 6, l = n0 & 63;
#pragma unroll
            for (int rr = 0; rr < 2; rr++) {
                int m0 = bm + warp_m * 64 + mi * 16 + er + rr * 8;
                float v0 = acc[mi][ni][rr * 2 + 0];
                float v1 = acc[mi][ni][rr * 2 + 1];
                __half2 hp = __floats2half2_rn(v0, v1);
                __half2 lp = __floats2half2_rn(v0 - __half2float(__low2half(hp)),
                                               v1 - __half2float(__high2half(hp)));
                size_t base = ((size_t)m0 * NH + h) * 128 + l;
                *(__half2*)(Qh + base)      = hp;   // hi
                *(__half2*)(Qh + base + 64) = lp;   // lo (qsum precision only)
            }
        }
    }
}

// ---- cvt_kv: lpart[8][T][128] -> lkh fp16 [T][64], lvTh [64][T], ksum ----
__global__ __launch_bounds__(256) void cvt_kv(
    const float* __restrict__ lpart, __half* __restrict__ lkh,
    __half* __restrict__ lvTh, float* __restrict__ ksum)
{
    __shared__ __half vh[64][65];
    __shared__ float kvs[64][65];
    const int t0 = blockIdx.x * 64;
    const int tid = threadIdx.x;
    for (int i = tid; i < 64 * 64; i += 256) {
        int r = i >> 6, l = i & 63;
        size_t idx = (size_t)(t0 + r) * 128 + l;
        float kv = 0.f, vv = 0.f;
#pragma unroll
        for (int s = 0; s < 8; s++) {
            kv += lpart[(size_t)s * T_SEQ * 128 + idx];
            vv += lpart[(size_t)s * T_SEQ * 128 + idx + 64];
        }
        vh[l][r] = __float2half(vv);
        kvs[r][l] = kv;
        lkh[(size_t)(t0 + r) * 64 + l] = __float2half(kv);
    }
    __syncthreads();
    for (int i = tid; i < 64 * 64; i += 256) {
        int l = i >> 6, r = i & 63;
        lvTh[(size_t)l * T_SEQ + t0 + r] = vh[l][r];
    }
    if (tid < 64) {
        float s = 0.f;
#pragma unroll 8
        for (int l = 0; l < 64; l++) s += kvs[tid][l];
        ksum[t0 + tid] = s;
    }
}

// ---------------- qsum from fp16 qlat hi+lo (recovers fp32 accumulator) ----------------
__global__ void qsum_kernel(const __half* __restrict__ qlath, float* __restrict__ qsum)
{
    int i = blockIdx.x * blockDim.x + threadIdx.x;
    if (i >= T_SEQ * NH) return;
    float s = 0.f;
#pragma unroll 8
    for (int l = 0; l < LAT; l++)
        s += __half2float(qlath[(size_t)i * 128 + l]) +
             __half2float(qlath[(size_t)i * 128 + 64 + l]);
    qsum[i] = s;
}

// ========== FA2-style fp16 flash, paired q-tiles ==========
#define FQS 72
#define FVS 136
#define FLASH_SMEM ((128 * FQS + 2 * 64 * FQS + 2 * 80 * FVS) * 2)   // 80384

__global__ __launch_bounds__(256) void flash_hmma(
    const __half* __restrict__ qlath, const __half* __restrict__ lkh,
    const __half* __restrict__ lvTh,
    const float* __restrict__ qsum, const float* __restrict__ ksum,
    __half* __restrict__ lctxh)
{
    extern __shared__ __align__(16) __half smh[];
    __half* Qs = smh;                      // 128 x FQS
    __half* Ks = Qs + 128 * FQS;           // 2 x 64 x FQS
    __half* VT = Ks + 2 * 64 * FQS;        // 2 x 80 x FVS
    __shared__ float kss[64];

    const int h = blockIdx.y;
    const int tid = threadIdx.x;
    const int lane = tid & 31;
    const int wid = tid >> 5;
    const int rm = wid * 16;

    const int a_row = lane & 15, a_koff = (lane >> 4) * 8;
    const int b_row = (lane & 7) + ((lane >> 4) & 1) * 8;
    const int b_koff = ((lane >> 3) & 1) * 8;
    const int er = lane >> 2, ec = (lane & 3) * 2;
    const float L2E = 1.4426950408889634f;

    // VT const rows 64..79: ones at row 64 (cols<64) -> row-sum column
    for (int i = tid; i < 2 * 16 * FVS; i += 256) {
        int buf = i / (16 * FVS);
        int rr = (i / FVS) % 16;
        int c = i % FVS;
        __half v = __ushort_as_half((unsigned short)0);
        if (rr == 0 && c < 64) v = __float2half(1.0f);
        VT[buf * 80 * FVS + (64 + rr) * FVS + c] = v;
    }

    auto load_kv = [&](int buf, int s0) {
        __half* ks = Ks + buf * 64 * FQS;
        __half* vt = VT + buf * 80 * FVS;
        for (int i = tid; i < 64 * 8; i += 256) {
            int r = i >> 3, c = i & 7;
            CP_ASYNC16(smem_u32(ks + r * FQS + c * 8),
                       lkh + (size_t)(s0 + r) * 64 + c * 8);
            CP_ASYNC16(smem_u32(vt + r * FVS + c * 8),
                       lvTh + (size_t)r * T_SEQ + s0 + c * 8);
        }
    };

#pragma unroll 1
    for (int pass = 0; pass < 2; pass++) {
        const int qt = pass == 0 ? (15 - blockIdx.x) : blockIdx.x;
        const int q0 = qt * 128;
        __syncthreads();

        // Q tile: hi half only ([t][h][128], first 64 cols)
        for (int i = tid; i < 128 * 8; i += 256) {
            int r = i >> 3, c = i & 7;
            CP_ASYNC16(smem_u32(Qs + r * FQS + c * 8),
                       qlath + ((size_t)(q0 + r) * NH + h) * 128 + c * 8);
        }
        load_kv(0, 0); CP_COMMIT();

        const float qss0 = qsum[(size_t)(q0 + rm + er) * NH + h] * 0.0625f;
        const float qss1 = qsum[(size_t)(q0 + rm + er + 8) * NH + h] * 0.0625f;
        const int gi0 = q0 + rm + er, gi1 = gi0 + 8;

        float Oa[9][4];
#pragma unroll
        for (int ni = 0; ni < 9; ni++)
#pragma unroll
            for (int r = 0; r < 4; r++) Oa[ni][r] = 0.f;
        float m0 = -1e30f, m1 = -1e30f;

        const int nkb = 2 * qt + 2;
        for (int kb = 0; kb < nkb; kb++) {
            const int buf = kb & 1;
            const int s0 = kb * 64;
            if (kb + 1 < nkb) { load_kv(buf ^ 1, (kb + 1) * 64); CP_COMMIT(); CP_WAIT1(); }
            else              { CP_WAIT0(); }
            if (tid < 64) kss[tid] = ksum[s0 + tid];
            __syncthreads();

            // ---- S = Q @ K^T (fp16, K=64) ----
            float sacc[8][4];
#pragma unroll
            for (int ni = 0; ni < 8; ni++)
#pragma unroll
                for (int r = 0; r < 4; r++) sacc[ni][r] = 0.f;
            const uint32_t aQrow = smem_u32(Qs) + ((rm + a_row) * FQS + a_koff) * 2;
            const uint32_t sKb = smem_u32(Ks) + (uint32_t)(buf * 64 * FQS) * 2;
#pragma unroll
            for (int kk = 0; kk < 64; kk += 16) {
                uint32_t af[4];
                ldmx4(af[0], af[1], af[2], af[3], aQrow + kk * 2);
                uint32_t bfr[8][2];
#pragma unroll
                for (int n4 = 0; n4 < 4; n4++) {
                    uint32_t r0, r1, r2, r3;
                    ldmx4(r0, r1, r2, r3, sKb + ((n4 * 16 + b_row) * FQS + kk + b_koff) * 2);
                    bfr[n4 * 2 + 0][0] = r0; bfr[n4 * 2 + 0][1] = r1;
                    bfr[n4 * 2 + 1][0] = r2; bfr[n4 * 2 + 1][1] = r3;
                }
#pragma unroll
                for (int ni = 0; ni < 8; ni++) mma16816h(sacc[ni], af, bfr[ni]);
            }

            // ---- scale + causal mask + reciprocal band ----
#pragma unroll
            for (int ni = 0; ni < 8; ni++) {
#pragma unroll
                for (int cc = 0; cc < 2; cc++) {
                    int gj = s0 + ni * 8 + ec + cc;
                    float ksv = kss[ni * 8 + ec + cc];
                    float v = sacc[ni][cc] * 0.125f;
                    if (gi0 - gj <= 64) v += qss0 * ksv;
                    sacc[ni][cc] = (gj <= gi0) ? v : -1e30f;
                    float w = sacc[ni][2 + cc] * 0.125f;
                    if (gi1 - gj <= 64) w += qss1 * ksv;
                    sacc[ni][2 + cc] = (gj <= gi1) ? w : -1e30f;
                }
            }

            // ---- online softmax on registers ----
            float mx0 = -1e30f, mx1 = -1e30f;
#pragma unroll
            for (int ni = 0; ni < 8; ni++) {
                mx0 = fmaxf(mx0, fmaxf(sacc[ni][0], sacc[ni][1]));
                mx1 = fmaxf(mx1, fmaxf(sacc[ni][2], sacc[ni][3]));
            }
            mx0 = fmaxf(mx0, __shfl_xor_sync(0xffffffffu, mx0, 1));
            mx0 = fmaxf(mx0, __shfl_xor_sync(0xffffffffu, mx0, 2));
            mx1 = fmaxf(mx1, __shfl_xor_sync(0xffffffffu, mx1, 1));
            mx1 = fmaxf(mx1, __shfl_xor_sync(0xffffffffu, mx1, 2));
            float mn0 = fmaxf(m0, mx0), mn1 = fmaxf(m1, mx1);
            float al0 = exp2f((m0 - mn0) * L2E);
            float al1 = exp2f((m1 - mn1) * L2E);
            m0 = mn0; m1 = mn1;
#pragma unroll
            for (int ni = 0; ni < 9; ni++) {
                Oa[ni][0] *= al0; Oa[ni][1] *= al0;
                Oa[ni][2] *= al1; Oa[ni][3] *= al1;
            }
            uint32_t p01[8], p23[8];
#pragma unroll
            for (int ni = 0; ni < 8; ni++) {
                float x0 = (sacc[ni][0] - mn0) * L2E;
                float x1 = (sacc[ni][1] - mn0) * L2E;
                float x2 = (sacc[ni][2] - mn1) * L2E;
                float x3 = (sacc[ni][3] - mn1) * L2E;
                uint32_t hx;
                asm("cvt.rn.f16x2.f32 %0, %1, %2;" : "=r"(hx) : "f"(x1), "f"(x0));
                asm("ex2.approx.f16x2 %0, %1;" : "=r"(p01[ni]) : "r"(hx));
                asm("cvt.rn.f16x2.f32 %0, %1, %2;" : "=r"(hx) : "f"(x3), "f"(x2));
                asm("ex2.approx.f16x2 %0, %1;" : "=r"(p23[ni]) : "r"(hx));
            }

            // ---- O += P @ V^T (fp16; col 64 = ones -> row sum) ----
            const uint32_t sVb = smem_u32(VT) + (uint32_t)(buf * 80 * FVS) * 2;
#pragma unroll
            for (int kk = 0; kk < 64; kk += 16) {
                int f = kk >> 3;
                uint32_t af[4] = { p01[f], p23[f], p01[f + 1], p23[f + 1] };
                uint32_t bfr[10][2];
#pragma unroll
                for (int n4 = 0; n4 < 5; n4++) {
                    uint32_t r0, r1, r2, r3;
                    ldmx4(r0, r1, r2, r3,
                          sVb + ((n4 * 16 + b_row) * FVS + kk + b_koff) * 2);
                    bfr[n4 * 2 + 0][0] = r0; bfr[n4 * 2 + 0][1] = r1;
                    bfr[n4 * 2 + 1][0] = r2; bfr[n4 * 2 + 1][1] = r3;
                }
#pragma unroll
                for (int ni = 0; ni < 9; ni++) mma16816h(Oa[ni], af, bfr[ni]);
            }
            __syncthreads();
        }

        // ---- epilogue: normalize, write fp16 lctx ----
        float ls0 = __shfl_sync(0xffffffffu, Oa[8][0], lane & ~3);
        float ls1 = __shfl_sync(0xffffffffu, Oa[8][2], lane & ~3);
        float li0 = 1.f / ls0, li1 = 1.f / ls1;
        const int t0 = q0 + rm + er, t1 = t0 + 8;
#pragma unroll
        for (int ni = 0; ni < 8; ni++) {
            int c0 = ni * 8 + ec;
            __half2 o0 = __floats2half2_rn(Oa[ni][0] * li0, Oa[ni][1] * li0);
            __half2 o1 = __floats2half2_rn(Oa[ni][2] * li1, Oa[ni][3] * li1);
            *(__half2*)(lctxh + (size_t)t0 * (NH * LAT) + h * 64 + c0) = o0;
            *(__half2*)(lctxh + (size_t)t1 * (NH * LAT) + h * 64 + c0) = o1;
        }
    }
}

// ---------------- host launcher ----------------
extern "C" void kernel_launch(void* const* d_in, const int* in_sizes, int n_in,
                              void* d_out, int out_size)
{
    const float* hidden = (const float*)d_in[0];
    const float* Wq  = (const float*)d_in[1];
    const float* Wk  = (const float*)d_in[2];
    const float* Wv  = (const float*)d_in[3];
    const float* q2l = (const float*)d_in[4];
    const float* vup = (const float*)d_in[5];
    const float* Wo  = (const float*)d_in[6];
    float* out = (float*)d_out;

    float *q2lT, *lpart, *qs, *ks;
    __nv_bfloat16 *WqT2, *Wo2, *q2l2p, *vup2p;
    __half *hidh, *Wkvh, *Wf1h, *Wf2h, *qlath, *lkh, *lvTh, *lctxh;
    cudaGetSymbolAddress((void**)&q2lT,  g_q2lT);
    cudaGetSymbolAddress((void**)&lpart, g_lpart);
    cudaGetSymbolAddress((void**)&qs,    g_qsum);
    cudaGetSymbolAddress((void**)&ks,    g_ksum);
    cudaGetSymbolAddress((void**)&WqT2,  g_WqT2);
    cudaGetSymbolAddress((void**)&Wo2,   g_Wo2);
    cudaGetSymbolAddress((void**)&q2l2p, g_q2l2p);
    cudaGetSymbolAddress((void**)&vup2p, g_vup2p);
    cudaGetSymbolAddress((void**)&hidh,  g_hidh);
    cudaGetSymbolAddress((void**)&Wkvh,  g_Wkvh);
    cudaGetSymbolAddress((void**)&Wf1h,  g_Wf1h);
    cudaGetSymbolAddress((void**)&Wf2h,  g_Wf2h);
    cudaGetSymbolAddress((void**)&qlath, g_qlath);
    cudaGetSymbolAddress((void**)&lkh,   g_lkh);
    cudaGetSymbolAddress((void**)&lvTh,  g_lvTh);
    cudaGetSymbolAddress((void**)&lctxh, g_lctxh);

    cudaFuncSetAttribute(hmma_gemm_f16,
                         cudaFuncAttributeMaxDynamicSharedMemorySize, HMMA_SMEM);
    cudaFuncSetAttribute(hmma_qlat_f16,
                         cudaFuncAttributeMaxDynamicSharedMemorySize, HMMA_SMEM);
    cudaFuncSetAttribute(hmma_fold,
                         cudaFuncAttributeMaxDynamicSharedMemorySize, HMMA_SMEM);
    cudaFuncSetAttribute(flash_hmma,
                         cudaFuncAttributeMaxDynamicSharedMemorySize, FLASH_SMEM);

    // --- weight preprocessing (folds stay bf16x3 for weight precision) ---
    transpose_k<<<dim3(2, 4, NH), dim3(32, 8)>>>(q2l, q2lT, HD, LAT,
                                                 (long)HD * LAT, (long)LAT * HD);
    transpose_split2<<<dim3(64, 64), dim3(32, 8)>>>(Wq, WqT2);
    cvt_split2<<<(EMB * EMB / 4 + 255) / 256, 256>>>(Wo, Wo2, EMB * EMB, HD, HD);
    cvt_split2_pad<<<(NH * HD * HD / 4 + 255) / 256, 256>>>(
        q2lT, q2l2p, NH, LAT, HD, HD, HD);
    cvt_split2_pad<<<(NH * HD * HD / 4 + 255) / 256, 256>>>(
        vup, vup2p, NH, LAT, HD, HD, HD);

    // --- folds (bf16x3 in, fp16 out) ---
    hmma_fold<<<dim3(16, 1, NH), 256, HMMA_SMEM>>>(
        q2l2p, WqT2, Wf1h, HD, 2 * HD, NH * 2 * HD,
        (long)HD * 2 * HD, (long)2 * HD, (long)LAT * EMB,
        EMB, LAT, EMB);
    hmma_fold<<<dim3(1, 16, NH), 256, HMMA_SMEM>>>(
        Wo2, vup2p, Wf2h, HD, NH * 2 * HD, 2 * HD,
        (long)2 * HD, (long)HD * 2 * HD, (long)LAT,
        NH * LAT, EMB, LAT);

    // --- fp16 input conversions ---
    cvt_f16<<<(T_SEQ * EMB / 4 + 255) / 256, 256>>>(hidden, hidh, T_SEQ * EMB);
    cvt_f16<<<(LAT * EMB / 4 + 255) / 256, 256>>>(Wk, Wkvh, LAT * EMB);
    cvt_f16<<<(LAT * EMB / 4 + 255) / 256, 256>>>(Wv, Wkvh + (size_t)LAT * EMB, LAT * EMB);

    // --- lkv = hid @ [Wk;Wv]^T (fp16, split-K x8; reduce fused in cvt_kv) ---
    hmma_gemm_f16<<<dim3(1, 16, 8), 256, HMMA_SMEM>>>(hidh, Wkvh, lpart,
                                                      T_SEQ, 2 * LAT, EMB, 8);
    cvt_kv<<<32, 256>>>(lpart, lkh, lvTh, ks);

    // --- q_latent (fp16, writes hi/lo for accurate qsum) ---
    hmma_qlat_f16<<<dim3(8, 16), 256, HMMA_SMEM>>>(hidh, Wf1h, qlath, EMB);
    qsum_kernel<<<(T_SEQ * NH + 255) / 256, 256>>>(qlath, qs);

    // --- flash attention (fp16) ---
    flash_hmma<<<dim3(8, NH), 256, FLASH_SMEM>>>(qlath, lkh, lvTh, qs, ks, lctxh);

    // --- out = lctx @ Wf2^T (fp16, K=1024) ---
    hmma_gemm_f16<<<dim3(16, 16, 1), 256, HMMA_SMEM>>>(lctxh, Wf2h, out,
                                                       T_SEQ, EMB, NH * LAT, 1);
}